// round 1
// baseline (speedup 1.0000x reference)
#include <cuda_runtime.h>
#include <cstdint>
#include <cstddef>

#define BB 64
#define NPTS 512
#define BNODES (BB*NPTS)     /* 32768 */
#define KNN 8
#define NEDGE (BNODES*KNN)   /* 262144 */
#define SLOPE 0.01f

// ---------------- scratch (device globals; no allocation allowed) ----------
__device__ float g_X1[BNODES*256];
__device__ float g_X2[BNODES*256];
__device__ float g_X3[BNODES*256];
__device__ float g_X4[BNODES*256];
__device__ float g_D[(size_t)BB*NPTS*NPTS];          // 64 MB
__device__ int   g_idx[NEDGE];
__device__ float g_U[BNODES*336];
__device__ float g_V[BNODES*336];
__device__ float g_H1[(size_t)NEDGE*336];            // 336 MB
__device__ float g_H2[(size_t)NEDGE*256];            // 256 MB
__device__ float g_CAT[(size_t)BNODES*1032];         // padded to 1032 for alignment
__device__ float g_Wd[256*336];
__device__ float g_norm[BNODES];
__device__ float g_POOL[BB*256];

__device__ __forceinline__ float lrelu(float x) { return x >= 0.f ? x : SLOPE * x; }

// ---------------- squared norms per node -----------------------------------
__global__ void norms_kernel(const float* __restrict__ X, int F) {
    int warp = (blockIdx.x * blockDim.x + threadIdx.x) >> 5;
    int lane = threadIdx.x & 31;
    if (warp >= BNODES) return;
    float s = 0.f;
    for (int f = lane; f < F; f += 32) {
        float v = X[(size_t)warp * F + f];
        s += v * v;
    }
    #pragma unroll
    for (int o = 16; o > 0; o >>= 1) s += __shfl_down_sync(0xffffffffu, s, o);
    if (lane == 0) g_norm[warp] = s;
}

// ---------------- pairwise distance matrix per batch (64x64 tiles) ----------
__global__ void dist_kernel(const float* __restrict__ X, int F) {
    __shared__ float Xi[16][64];
    __shared__ float Xj[16][64];
    int b  = blockIdx.z;
    int i0 = blockIdx.y * 64, j0 = blockIdx.x * 64;
    int tx = threadIdx.x, ty = threadIdx.y;
    int t  = ty * 16 + tx;
    int base = b * NPTS;
    float acc[4][4] = {};
    int lrow = t >> 2;
    int lcg  = (t & 3) * 4;
    for (int f0 = 0; f0 < F; f0 += 16) {
        #pragma unroll
        for (int e = 0; e < 4; e++) {
            int f = f0 + lcg + e;
            Xi[lcg + e][lrow] = (f < F) ? X[(size_t)(base + i0 + lrow) * F + f] : 0.f;
            Xj[lcg + e][lrow] = (f < F) ? X[(size_t)(base + j0 + lrow) * F + f] : 0.f;
        }
        __syncthreads();
        #pragma unroll
        for (int k = 0; k < 16; k++) {
            float a[4], c[4];
            #pragma unroll
            for (int e = 0; e < 4; e++) { a[e] = Xi[k][ty * 4 + e]; c[e] = Xj[k][tx * 4 + e]; }
            #pragma unroll
            for (int u = 0; u < 4; u++)
                #pragma unroll
                for (int v = 0; v < 4; v++) acc[u][v] = fmaf(a[u], c[v], acc[u][v]);
        }
        __syncthreads();
    }
    #pragma unroll
    for (int u = 0; u < 4; u++) {
        int i = i0 + ty * 4 + u;
        float ni = g_norm[base + i];
        #pragma unroll
        for (int v = 0; v < 4; v++) {
            int j = j0 + tx * 4 + v;
            g_D[(size_t)(base + i) * NPTS + j] = ni + g_norm[base + j] - 2.f * acc[u][v];
        }
    }
}

// ---------------- k=8 smallest per row (tie-break: lowest index) ------------
__global__ void topk_kernel() {
    int node = (blockIdx.x * blockDim.x + threadIdx.x) >> 5;
    int lane = threadIdx.x & 31;
    if (node >= BNODES) return;
    int b = node / NPTS;
    const float* drow = &g_D[(size_t)node * NPTS];
    float v[16];
    #pragma unroll
    for (int s = 0; s < 16; s++) v[s] = drow[lane + 32 * s];
    for (int it = 0; it < KNN; it++) {
        float bv = 3.4e38f;
        int   bi = 1 << 20;
        #pragma unroll
        for (int s = 0; s < 16; s++) {
            int j = lane + 32 * s;
            if (v[s] < bv) { bv = v[s]; bi = j; }   // ascending j -> keeps lowest idx on tie
        }
        #pragma unroll
        for (int o = 16; o > 0; o >>= 1) {
            float ov = __shfl_down_sync(0xffffffffu, bv, o);
            int   oi = __shfl_down_sync(0xffffffffu, bi, o);
            if (ov < bv || (ov == bv && oi < bi)) { bv = ov; bi = oi; }
        }
        int wi = __shfl_sync(0xffffffffu, bi, 0);
        if (lane == (wi & 31)) v[wi >> 5] = 3.4e38f;
        if (lane == 0) g_idx[node * KNN + it] = b * NPTS + wi;
    }
}

// ---------------- W1a - W1b (enables per-node factorization of GEMM1) ------
__global__ void wdiff_kernel(const float* __restrict__ W1, int F) {
    int i = blockIdx.x * blockDim.x + threadIdx.x;
    if (i < F * 336) g_Wd[i] = W1[i] - W1[F * 336 + i];
}

// ---------------- generic fp32 GEMM 128x128x8, bias + optional LeakyReLU ---
// C[M,Nd] = act(A[M,Kd](lda) @ W[Kd,Nd] + bias).  M % 128 == 0 always here.
__global__ __launch_bounds__(256, 2) void gemm_kernel(
    const float* __restrict__ A, const float* __restrict__ W,
    const float* __restrict__ bias, float* __restrict__ C,
    int M, int Kd, int Nd, int lda, int act)
{
    __shared__ float As[8][128];
    __shared__ float Bs[8][128];
    int bm = blockIdx.y * 128, bn = blockIdx.x * 128;
    int t = threadIdx.x;
    int arow = t >> 1, acg = (t & 1) * 4;
    int bkr = t >> 5,  bcol = (t & 31) * 4;
    int ty = t >> 4, tx = t & 15;
    int rowb = ty * 8, colb = tx * 8;
    float acc[8][8] = {};

    for (int k0 = 0; k0 < Kd; k0 += 8) {
        if (k0 + 8 <= Kd) {
            float4 av = *(const float4*)&A[(size_t)(bm + arow) * lda + k0 + acg];
            As[acg + 0][arow] = av.x; As[acg + 1][arow] = av.y;
            As[acg + 2][arow] = av.z; As[acg + 3][arow] = av.w;
        } else {
            #pragma unroll
            for (int e = 0; e < 4; e++) {
                int f = k0 + acg + e;
                As[acg + e][arow] = (f < Kd) ? A[(size_t)(bm + arow) * lda + f] : 0.f;
            }
        }
        if (k0 + bkr < Kd) {
            if (bn + bcol + 4 <= Nd) {
                *(float4*)&Bs[bkr][bcol] = *(const float4*)&W[(size_t)(k0 + bkr) * Nd + bn + bcol];
            } else {
                #pragma unroll
                for (int e = 0; e < 4; e++) {
                    int c = bn + bcol + e;
                    Bs[bkr][bcol + e] = (c < Nd) ? W[(size_t)(k0 + bkr) * Nd + c] : 0.f;
                }
            }
        } else {
            *(float4*)&Bs[bkr][bcol] = make_float4(0.f, 0.f, 0.f, 0.f);
        }
        __syncthreads();
        #pragma unroll
        for (int k = 0; k < 8; k++) {
            float a[8], bb[8];
            *(float4*)(a)      = *(float4*)&As[k][rowb];
            *(float4*)(a + 4)  = *(float4*)&As[k][rowb + 4];
            *(float4*)(bb)     = *(float4*)&Bs[k][colb];
            *(float4*)(bb + 4) = *(float4*)&Bs[k][colb + 4];
            #pragma unroll
            for (int u = 0; u < 8; u++)
                #pragma unroll
                for (int v = 0; v < 8; v++) acc[u][v] = fmaf(a[u], bb[v], acc[u][v]);
        }
        __syncthreads();
    }
    float bv[8];
    #pragma unroll
    for (int v = 0; v < 8; v++) {
        int c = bn + colb + v;
        bv[v] = (bias != nullptr && c < Nd) ? bias[c] : 0.f;
    }
    #pragma unroll
    for (int u = 0; u < 8; u++) {
        int r = bm + rowb + u;
        #pragma unroll
        for (int v = 0; v < 8; v++) {
            int c = bn + colb + v;
            if (c < Nd) {
                float x = acc[u][v] + bv[v];
                if (act) x = lrelu(x);
                C[(size_t)r * Nd + c] = x;
            }
        }
    }
}

// ---------------- H1[edge] = lrelu(U[i] + V[j] + b1) ------------------------
__global__ void combine_kernel(const float* __restrict__ b1) {
    int node = blockIdx.x;
    int t = threadIdx.x;
    if (t >= 336) return;
    float u = g_U[node * 336 + t] + b1[t];
    #pragma unroll
    for (int k = 0; k < KNN; k++) {
        int j = g_idx[node * KNN + k];
        float h = u + g_V[j * 336 + t];
        g_H1[(size_t)(node * KNN + k) * 336 + t] = lrelu(h);
    }
}

// ---------------- max over K neighbors --------------------------------------
__global__ void maxk_kernel(float* __restrict__ Xout) {
    int node = blockIdx.x, t = threadIdx.x;  // 256 threads
    float m = -3.4e38f;
    #pragma unroll
    for (int k = 0; k < KNN; k++)
        m = fmaxf(m, g_H2[(size_t)(node * KNN + k) * 256 + t]);
    Xout[node * 256 + t] = m;
}

// ---------------- concat [x0, x1, x2, x3, x4] -> [32768, 1030] (pad 1032) ---
__global__ void concat_kernel(const float* __restrict__ X0) {
    int node = blockIdx.x, t = threadIdx.x;  // 256 threads
    float* row = &g_CAT[(size_t)node * 1032];
    if (t < 6) row[t] = X0[node * 6 + t];
    row[6   + t] = g_X1[node * 256 + t];
    row[262 + t] = g_X2[node * 256 + t];
    row[518 + t] = g_X3[node * 256 + t];
    row[774 + t] = g_X4[node * 256 + t];
}

// ---------------- mean-pool over the 512 nodes of each batch ----------------
__global__ void pool_kernel() {
    int b = blockIdx.x, t = threadIdx.x;  // 256 threads
    float s = 0.f;
    for (int i = 0; i < NPTS; i++)
        s += g_H2[(size_t)(b * NPTS + i) * 256 + t];
    g_POOL[b * 256 + t] = s * (1.f / NPTS);
}

// ---------------- head: lrelu(g@W1+b1)@W2+b2 --------------------------------
__global__ void final_kernel(const float* __restrict__ w1, const float* __restrict__ b1,
                             const float* __restrict__ w2, const float* __restrict__ b2,
                             float* __restrict__ out) {
    __shared__ float h[128];
    int b = blockIdx.x, t = threadIdx.x;  // 128 threads
    float acc = b1[t];
    for (int c = 0; c < 256; c++) acc = fmaf(g_POOL[b * 256 + c], w1[c * 128 + t], acc);
    h[t] = lrelu(acc);
    __syncthreads();
    if (t < 3) {
        float o = b2[t];
        for (int c = 0; c < 128; c++) o = fmaf(h[c], w2[c * 3 + t], o);
        out[b * 3 + t] = o;
    }
}

// ---------------- launcher ---------------------------------------------------
extern "C" void kernel_launch(void* const* d_in, const int* in_sizes, int n_in,
                              void* d_out, int out_size) {
    (void)in_sizes; (void)n_in; (void)out_size;
    const float* x0 = (const float*)d_in[0];
    const float* cw1[4] = { (const float*)d_in[3],  (const float*)d_in[7],
                            (const float*)d_in[11], (const float*)d_in[15] };
    const float* cb1[4] = { (const float*)d_in[4],  (const float*)d_in[8],
                            (const float*)d_in[12], (const float*)d_in[16] };
    const float* cw2[4] = { (const float*)d_in[5],  (const float*)d_in[9],
                            (const float*)d_in[13], (const float*)d_in[17] };
    const float* cb2[4] = { (const float*)d_in[6],  (const float*)d_in[10],
                            (const float*)d_in[14], (const float*)d_in[18] };
    const float* m1w1 = (const float*)d_in[19];
    const float* m1b1 = (const float*)d_in[20];
    const float* m1w2 = (const float*)d_in[21];
    const float* m1b2 = (const float*)d_in[22];
    const float* m2w1 = (const float*)d_in[23];
    const float* m2b1 = (const float*)d_in[24];
    const float* m2w2 = (const float*)d_in[25];
    const float* m2b2 = (const float*)d_in[26];

    void* p;
    float *pX[4], *pU, *pV, *pH1, *pH2, *pCAT, *pWd;
    cudaGetSymbolAddress(&p, g_X1); pX[0] = (float*)p;
    cudaGetSymbolAddress(&p, g_X2); pX[1] = (float*)p;
    cudaGetSymbolAddress(&p, g_X3); pX[2] = (float*)p;
    cudaGetSymbolAddress(&p, g_X4); pX[3] = (float*)p;
    cudaGetSymbolAddress(&p, g_U);   pU   = (float*)p;
    cudaGetSymbolAddress(&p, g_V);   pV   = (float*)p;
    cudaGetSymbolAddress(&p, g_H1);  pH1  = (float*)p;
    cudaGetSymbolAddress(&p, g_H2);  pH2  = (float*)p;
    cudaGetSymbolAddress(&p, g_CAT); pCAT = (float*)p;
    cudaGetSymbolAddress(&p, g_Wd);  pWd  = (float*)p;

    for (int l = 0; l < 4; l++) {
        const float* Xin = (l == 0) ? x0 : pX[l - 1];
        int F = (l == 0) ? 6 : 256;

        norms_kernel<<<BNODES / 8, 256>>>(Xin, F);
        dist_kernel<<<dim3(8, 8, BB), dim3(16, 16)>>>(Xin, F);
        topk_kernel<<<BNODES * 32 / 128, 128>>>();
        wdiff_kernel<<<(F * 336 + 255) / 256, 256>>>(cw1[l], F);
        // U = Xin @ (W1a - W1b)      [BNODES, 336]
        gemm_kernel<<<dim3(3, BNODES / 128), 256>>>(Xin, pWd, nullptr, pU,
                                                    BNODES, F, 336, F, 0);
        // V = Xin @ W1b              [BNODES, 336]
        gemm_kernel<<<dim3(3, BNODES / 128), 256>>>(Xin, cw1[l] + (size_t)F * 336, nullptr, pV,
                                                    BNODES, F, 336, F, 0);
        combine_kernel<<<BNODES, 352>>>(cb1[l]);
        // H2 = lrelu(H1 @ W2 + b2)   [NEDGE, 256]
        gemm_kernel<<<dim3(2, NEDGE / 128), 256>>>(pH1, cw2[l], cb2[l], pH2,
                                                   NEDGE, 336, 256, 336, 1);
        maxk_kernel<<<BNODES, 256>>>(pX[l]);
    }

    concat_kernel<<<BNODES, 256>>>(x0);
    // m1: 1030 -> 336 -> 256, both LeakyReLU
    gemm_kernel<<<dim3(3, BNODES / 128), 256>>>(pCAT, m1w1, m1b1, pH1,
                                                BNODES, 1030, 336, 1032, 1);
    gemm_kernel<<<dim3(2, BNODES / 128), 256>>>(pH1, m1w2, m1b2, pH2,
                                                BNODES, 336, 256, 336, 1);
    pool_kernel<<<BB, 256>>>();
    final_kernel<<<BB, 128>>>(m2w1, m2b1, m2w2, m2b2, (float*)d_out);
}

// round 2
// speedup vs baseline: 2.1368x; 2.1368x over previous
#include <cuda_runtime.h>
#include <cstdint>
#include <cstddef>

#define BB 64
#define NPTS 512
#define BNODES (BB*NPTS)     /* 32768 */
#define KNN 8
#define NEDGE (BNODES*KNN)   /* 262144 */
#define SLOPE 0.01f

// ---------------- scratch (device globals; no allocation allowed) ----------
__device__ float g_X1[BNODES*256];
__device__ float g_X2[BNODES*256];
__device__ float g_X3[BNODES*256];
__device__ float g_X4[BNODES*256];
__device__ float g_D[(size_t)BB*NPTS*NPTS];          // 64 MB
__device__ int   g_idx[NEDGE];
__device__ float g_U[BNODES*336];
__device__ float g_V[BNODES*336];
__device__ float g_H1[(size_t)BNODES*336];           // m1 intermediate
__device__ float g_H2[(size_t)BNODES*256];           // m1 output
__device__ float g_CAT[(size_t)BNODES*1040];         // padded 1030 -> 1040
__device__ float g_Wd[256*336];
__device__ float g_norm[BNODES];
__device__ float g_POOL[BB*256];

__device__ __forceinline__ float lrelu(float x) { return x >= 0.f ? x : SLOPE * x; }

__device__ __forceinline__ float f2tf32(float x) {
    uint32_t r;
    asm("cvt.rna.tf32.f32 %0, %1;" : "=r"(r) : "f"(x));
    return __uint_as_float(r);
}

__device__ __forceinline__ void mma_tf32(float* c, const uint32_t* a, const uint32_t* b) {
    asm volatile(
        "mma.sync.aligned.m16n8k8.row.col.f32.tf32.tf32.f32 "
        "{%0,%1,%2,%3}, {%4,%5,%6,%7}, {%8,%9}, {%0,%1,%2,%3};\n"
        : "+f"(c[0]), "+f"(c[1]), "+f"(c[2]), "+f"(c[3])
        : "r"(a[0]), "r"(a[1]), "r"(a[2]), "r"(a[3]), "r"(b[0]), "r"(b[1]));
}

// ---------------- squared norms per node -----------------------------------
__global__ void norms_kernel(const float* __restrict__ X, int F) {
    int warp = (blockIdx.x * blockDim.x + threadIdx.x) >> 5;
    int lane = threadIdx.x & 31;
    if (warp >= BNODES) return;
    float s = 0.f;
    for (int f = lane; f < F; f += 32) {
        float v = X[(size_t)warp * F + f];
        s += v * v;
    }
    #pragma unroll
    for (int o = 16; o > 0; o >>= 1) s += __shfl_down_sync(0xffffffffu, s, o);
    if (lane == 0) g_norm[warp] = s;
}

// ---------------- pairwise distances: 128x128 tile, 8x8 microkernel ---------
__global__ __launch_bounds__(256) void dist_kernel(const float* __restrict__ X, int F) {
    __shared__ float Xa[8][132];
    __shared__ float Xb[8][132];
    int b  = blockIdx.z;
    int i0 = blockIdx.y * 128, j0 = blockIdx.x * 128;
    int base = b * NPTS;
    int t = threadIdx.x;
    int arow = t >> 1, kg = (t & 1) * 4;
    int ty = t >> 4, tx = t & 15;
    int rowb = ty * 8, colb = tx * 8;
    float acc[8][8] = {};

    for (int k0 = 0; k0 < F; k0 += 8) {
        if (k0 + 8 <= F) {
            float4 a = *(const float4*)&X[(size_t)(base + i0 + arow) * F + k0 + kg];
            Xa[kg + 0][arow] = a.x; Xa[kg + 1][arow] = a.y;
            Xa[kg + 2][arow] = a.z; Xa[kg + 3][arow] = a.w;
            float4 c = *(const float4*)&X[(size_t)(base + j0 + arow) * F + k0 + kg];
            Xb[kg + 0][arow] = c.x; Xb[kg + 1][arow] = c.y;
            Xb[kg + 2][arow] = c.z; Xb[kg + 3][arow] = c.w;
        } else {
            #pragma unroll
            for (int e = 0; e < 4; e++) {
                int f = k0 + kg + e;
                Xa[kg + e][arow] = (f < F) ? X[(size_t)(base + i0 + arow) * F + f] : 0.f;
                Xb[kg + e][arow] = (f < F) ? X[(size_t)(base + j0 + arow) * F + f] : 0.f;
            }
        }
        __syncthreads();
        #pragma unroll
        for (int k = 0; k < 8; k++) {
            float a[8], c[8];
            *(float4*)(a)     = *(float4*)&Xa[k][rowb];
            *(float4*)(a + 4) = *(float4*)&Xa[k][rowb + 4];
            *(float4*)(c)     = *(float4*)&Xb[k][colb];
            *(float4*)(c + 4) = *(float4*)&Xb[k][colb + 4];
            #pragma unroll
            for (int u = 0; u < 8; u++)
                #pragma unroll
                for (int v = 0; v < 8; v++) acc[u][v] = fmaf(a[u], c[v], acc[u][v]);
        }
        __syncthreads();
    }
    #pragma unroll
    for (int u = 0; u < 8; u++) {
        int i = i0 + rowb + u;
        float ni = g_norm[base + i];
        #pragma unroll
        for (int v = 0; v < 8; v++) {
            int j = j0 + colb + v;
            g_D[(size_t)(base + i) * NPTS + j] = ni + g_norm[base + j] - 2.f * acc[u][v];
        }
    }
}

// ---------------- k=8 smallest per row (tie-break: lowest index) ------------
__global__ void topk_kernel() {
    int node = (blockIdx.x * blockDim.x + threadIdx.x) >> 5;
    int lane = threadIdx.x & 31;
    if (node >= BNODES) return;
    int b = node / NPTS;
    const float* drow = &g_D[(size_t)node * NPTS];
    float v[16];
    #pragma unroll
    for (int s = 0; s < 16; s++) v[s] = drow[lane + 32 * s];
    for (int it = 0; it < KNN; it++) {
        float bv = 3.4e38f;
        int   bi = 1 << 20;
        #pragma unroll
        for (int s = 0; s < 16; s++) {
            int j = lane + 32 * s;
            if (v[s] < bv) { bv = v[s]; bi = j; }
        }
        #pragma unroll
        for (int o = 16; o > 0; o >>= 1) {
            float ov = __shfl_down_sync(0xffffffffu, bv, o);
            int   oi = __shfl_down_sync(0xffffffffu, bi, o);
            if (ov < bv || (ov == bv && oi < bi)) { bv = ov; bi = oi; }
        }
        int wi = __shfl_sync(0xffffffffu, bi, 0);
        if (lane == (wi & 31)) v[wi >> 5] = 3.4e38f;
        if (lane == 0) g_idx[node * KNN + it] = b * NPTS + wi;
    }
}

// ---------------- W1a - W1b -------------------------------------------------
__global__ void wdiff_kernel(const float* __restrict__ W1, int F) {
    int i = blockIdx.x * blockDim.x + threadIdx.x;
    if (i < F * 336) g_Wd[i] = W1[i] - W1[F * 336 + i];
}

// ---------------- fp32 GEMM (only for layer-0 U/V, K=6) --------------------
__global__ __launch_bounds__(256, 2) void gemm_kernel(
    const float* __restrict__ A, const float* __restrict__ W,
    const float* __restrict__ bias, float* __restrict__ C,
    int M, int Kd, int Nd, int lda, int act)
{
    __shared__ float As[8][128];
    __shared__ float Bs[8][128];
    int bm = blockIdx.y * 128, bn = blockIdx.x * 128;
    int t = threadIdx.x;
    int arow = t >> 1, acg = (t & 1) * 4;
    int bkr = t >> 5,  bcol = (t & 31) * 4;
    int ty = t >> 4, tx = t & 15;
    int rowb = ty * 8, colb = tx * 8;
    float acc[8][8] = {};

    for (int k0 = 0; k0 < Kd; k0 += 8) {
        #pragma unroll
        for (int e = 0; e < 4; e++) {
            int f = k0 + acg + e;
            As[acg + e][arow] = (f < Kd) ? A[(size_t)(bm + arow) * lda + f] : 0.f;
        }
        if (k0 + bkr < Kd) {
            #pragma unroll
            for (int e = 0; e < 4; e++) {
                int c = bn + bcol + e;
                Bs[bkr][bcol + e] = (c < Nd) ? W[(size_t)(k0 + bkr) * Nd + c] : 0.f;
            }
        } else {
            #pragma unroll
            for (int e = 0; e < 4; e++) Bs[bkr][bcol + e] = 0.f;
        }
        __syncthreads();
        #pragma unroll
        for (int k = 0; k < 8; k++) {
            float a[8], bb[8];
            *(float4*)(a)      = *(float4*)&As[k][rowb];
            *(float4*)(a + 4)  = *(float4*)&As[k][rowb + 4];
            *(float4*)(bb)     = *(float4*)&Bs[k][colb];
            *(float4*)(bb + 4) = *(float4*)&Bs[k][colb + 4];
            #pragma unroll
            for (int u = 0; u < 8; u++)
                #pragma unroll
                for (int v = 0; v < 8; v++) acc[u][v] = fmaf(a[u], bb[v], acc[u][v]);
        }
        __syncthreads();
    }
    #pragma unroll
    for (int u = 0; u < 8; u++) {
        int r = bm + rowb + u;
        #pragma unroll
        for (int v = 0; v < 8; v++) {
            int c = bn + colb + v;
            if (c < Nd) {
                float x = acc[u][v] + (bias ? bias[c] : 0.f);
                if (act) x = lrelu(x);
                C[(size_t)r * Nd + c] = x;
            }
        }
    }
}

// ---------------- generic tf32 tensor-core GEMM -----------------------------
// C[M,Nd] = act(A[M,Kd](lda) @ W[KBreal,Nd] + bias); Kd % 16 == 0, M % 128 == 0.
__global__ __launch_bounds__(256) void gemm_tf32_kernel(
    const float* __restrict__ A, const float* __restrict__ W,
    const float* __restrict__ bias, float* __restrict__ C,
    int Kd, int KBreal, int Nd, int lda, int act)
{
    __shared__ float As[16][136];
    __shared__ float Bs[16][136];
    int bm = blockIdx.y * 128, bn = blockIdx.x * 128;
    int t = threadIdx.x, lane = t & 31, wid = t >> 5;
    int warpM = wid & 1, warpN = wid >> 1;
    int arow = t >> 1, ahalf = (t & 1) * 8;
    int bk = t >> 4, bcq = (t & 15) * 8;
    int r = lane >> 2, cc = lane & 3;
    float acc[4][4][4] = {};

    for (int k0 = 0; k0 < Kd; k0 += 16) {
        const float* ap = &A[(size_t)(bm + arow) * lda + k0 + ahalf];
        float4 a0 = *(const float4*)ap;
        float4 a1 = *(const float4*)(ap + 4);
        As[ahalf + 0][arow] = f2tf32(a0.x); As[ahalf + 1][arow] = f2tf32(a0.y);
        As[ahalf + 2][arow] = f2tf32(a0.z); As[ahalf + 3][arow] = f2tf32(a0.w);
        As[ahalf + 4][arow] = f2tf32(a1.x); As[ahalf + 5][arow] = f2tf32(a1.y);
        As[ahalf + 6][arow] = f2tf32(a1.z); As[ahalf + 7][arow] = f2tf32(a1.w);
        if (k0 + bk < KBreal) {
            const float* wr = &W[(size_t)(k0 + bk) * Nd + bn + bcq];
            #pragma unroll
            for (int e = 0; e < 8; e++) {
                int c = bn + bcq + e;
                Bs[bk][bcq + e] = (c < Nd) ? f2tf32(wr[e]) : 0.f;
            }
        } else {
            #pragma unroll
            for (int e = 0; e < 8; e++) Bs[bk][bcq + e] = 0.f;
        }
        __syncthreads();
        #pragma unroll
        for (int kk = 0; kk < 2; kk++) {
            uint32_t af[4][4], bf[4][2];
            #pragma unroll
            for (int mf = 0; mf < 4; mf++) {
                int rb = warpM * 64 + mf * 16;
                af[mf][0] = __float_as_uint(As[kk*8 + cc    ][rb + r    ]);
                af[mf][1] = __float_as_uint(As[kk*8 + cc    ][rb + r + 8]);
                af[mf][2] = __float_as_uint(As[kk*8 + cc + 4][rb + r    ]);
                af[mf][3] = __float_as_uint(As[kk*8 + cc + 4][rb + r + 8]);
            }
            #pragma unroll
            for (int nf = 0; nf < 4; nf++) {
                int cb = warpN * 32 + nf * 8;
                bf[nf][0] = __float_as_uint(Bs[kk*8 + cc    ][cb + r]);
                bf[nf][1] = __float_as_uint(Bs[kk*8 + cc + 4][cb + r]);
            }
            #pragma unroll
            for (int mf = 0; mf < 4; mf++)
                #pragma unroll
                for (int nf = 0; nf < 4; nf++)
                    mma_tf32(acc[mf][nf], af[mf], bf[nf]);
        }
        __syncthreads();
    }
    #pragma unroll
    for (int mf = 0; mf < 4; mf++) {
        int r0 = bm + warpM * 64 + mf * 16 + r;
        #pragma unroll
        for (int nf = 0; nf < 4; nf++) {
            int cb = bn + warpN * 32 + nf * 8 + cc * 2;
            #pragma unroll
            for (int e = 0; e < 2; e++) {
                int c = cb + e;
                if (c < Nd) {
                    float bv = bias ? bias[c] : 0.f;
                    float x0 = acc[mf][nf][0 + e] + bv;
                    float x1 = acc[mf][nf][2 + e] + bv;
                    if (act) { x0 = lrelu(x0); x1 = lrelu(x1); }
                    C[(size_t)r0 * Nd + c]       = x0;
                    C[(size_t)(r0 + 8) * Nd + c] = x1;
                }
            }
        }
    }
}

// ---------------- fused edge GEMM2: A = lrelu(U[i]+V[j]+b1) on the fly,
// ---------------- epilogue = max over the 8 edges of each node + bias + lrelu
__global__ __launch_bounds__(256) void edge_gemm2_kernel(
    const float* __restrict__ b1, const float* __restrict__ W2,
    const float* __restrict__ b2, float* __restrict__ Xout)
{
    __shared__ float As[16][136];
    __shared__ float Bs[16][136];
    __shared__ int   jj[128];
    __shared__ float b1s[336];
    int bm = blockIdx.y * 128, bn = blockIdx.x * 128;   // bm: edge base, 128 edges = 16 nodes
    int t = threadIdx.x, lane = t & 31, wid = t >> 5;
    int warpM = wid & 1, warpN = wid >> 1;
    int arow = t >> 1, ahalf = (t & 1) * 8;
    int bk = t >> 4, bcq = (t & 15) * 8;
    int r = lane >> 2, cc = lane & 3;
    float acc[4][4][4] = {};

    if (t < 128) jj[t] = g_idx[bm + t];
    for (int s = t; s < 336; s += 256) b1s[s] = b1[s];
    __syncthreads();

    int i = (bm + arow) >> 3;          // center node of this edge row
    int j = jj[arow];                  // neighbor node

    for (int k0 = 0; k0 < 336; k0 += 16) {
        const float* up = &g_U[(size_t)i * 336 + k0 + ahalf];
        const float* vp = &g_V[(size_t)j * 336 + k0 + ahalf];
        float4 u0 = *(const float4*)up, u1 = *(const float4*)(up + 4);
        float4 v0 = *(const float4*)vp, v1 = *(const float4*)(vp + 4);
        const float* bp = &b1s[k0 + ahalf];
        As[ahalf + 0][arow] = f2tf32(lrelu(u0.x + v0.x + bp[0]));
        As[ahalf + 1][arow] = f2tf32(lrelu(u0.y + v0.y + bp[1]));
        As[ahalf + 2][arow] = f2tf32(lrelu(u0.z + v0.z + bp[2]));
        As[ahalf + 3][arow] = f2tf32(lrelu(u0.w + v0.w + bp[3]));
        As[ahalf + 4][arow] = f2tf32(lrelu(u1.x + v1.x + bp[4]));
        As[ahalf + 5][arow] = f2tf32(lrelu(u1.y + v1.y + bp[5]));
        As[ahalf + 6][arow] = f2tf32(lrelu(u1.z + v1.z + bp[6]));
        As[ahalf + 7][arow] = f2tf32(lrelu(u1.w + v1.w + bp[7]));
        {
            const float* wr = &W2[(size_t)(k0 + bk) * 256 + bn + bcq];
            float4 w0 = *(const float4*)wr, w1 = *(const float4*)(wr + 4);
            Bs[bk][bcq + 0] = f2tf32(w0.x); Bs[bk][bcq + 1] = f2tf32(w0.y);
            Bs[bk][bcq + 2] = f2tf32(w0.z); Bs[bk][bcq + 3] = f2tf32(w0.w);
            Bs[bk][bcq + 4] = f2tf32(w1.x); Bs[bk][bcq + 5] = f2tf32(w1.y);
            Bs[bk][bcq + 6] = f2tf32(w1.z); Bs[bk][bcq + 7] = f2tf32(w1.w);
        }
        __syncthreads();
        #pragma unroll
        for (int kk = 0; kk < 2; kk++) {
            uint32_t af[4][4], bf[4][2];
            #pragma unroll
            for (int mf = 0; mf < 4; mf++) {
                int rb = warpM * 64 + mf * 16;
                af[mf][0] = __float_as_uint(As[kk*8 + cc    ][rb + r    ]);
                af[mf][1] = __float_as_uint(As[kk*8 + cc    ][rb + r + 8]);
                af[mf][2] = __float_as_uint(As[kk*8 + cc + 4][rb + r    ]);
                af[mf][3] = __float_as_uint(As[kk*8 + cc + 4][rb + r + 8]);
            }
            #pragma unroll
            for (int nf = 0; nf < 4; nf++) {
                int cb = warpN * 32 + nf * 8;
                bf[nf][0] = __float_as_uint(Bs[kk*8 + cc    ][cb + r]);
                bf[nf][1] = __float_as_uint(Bs[kk*8 + cc + 4][cb + r]);
            }
            #pragma unroll
            for (int mf = 0; mf < 4; mf++)
                #pragma unroll
                for (int nf = 0; nf < 4; nf++)
                    mma_tf32(acc[mf][nf], af[mf], bf[nf]);
        }
        __syncthreads();
    }

    // Epilogue: warp tile = 64 rows = 8 full nodes. Max across the 8 edge-rows
    // of each node via butterfly shuffle over lanes {cc, cc+4, ..., cc+28}.
    int base_node = (bm >> 3) + warpM * 8;
    #pragma unroll
    for (int mf = 0; mf < 4; mf++) {
        #pragma unroll
        for (int nf = 0; nf < 4; nf++) {
            float v00 = acc[mf][nf][0], v01 = acc[mf][nf][1];
            float v10 = acc[mf][nf][2], v11 = acc[mf][nf][3];
            #pragma unroll
            for (int o = 4; o < 32; o <<= 1) {
                v00 = fmaxf(v00, __shfl_xor_sync(0xffffffffu, v00, o));
                v01 = fmaxf(v01, __shfl_xor_sync(0xffffffffu, v01, o));
                v10 = fmaxf(v10, __shfl_xor_sync(0xffffffffu, v10, o));
                v11 = fmaxf(v11, __shfl_xor_sync(0xffffffffu, v11, o));
            }
            if (lane < 4) {
                int col = bn + warpN * 32 + nf * 8 + cc * 2;
                int n0 = base_node + mf * 2, n1 = n0 + 1;
                Xout[(size_t)n0 * 256 + col    ] = lrelu(v00 + b2[col]);
                Xout[(size_t)n0 * 256 + col + 1] = lrelu(v01 + b2[col + 1]);
                Xout[(size_t)n1 * 256 + col    ] = lrelu(v10 + b2[col]);
                Xout[(size_t)n1 * 256 + col + 1] = lrelu(v11 + b2[col + 1]);
            }
        }
    }
}

// ---------------- concat [x0, x1, x2, x3, x4] -> [32768, 1030] (pad 1040) ---
__global__ void concat_kernel(const float* __restrict__ X0) {
    int node = blockIdx.x, t = threadIdx.x;  // 256 threads
    float* row = &g_CAT[(size_t)node * 1040];
    if (t < 6)  row[t] = X0[node * 6 + t];
    if (t < 10) row[1030 + t] = 0.f;
    row[6   + t] = g_X1[node * 256 + t];
    row[262 + t] = g_X2[node * 256 + t];
    row[518 + t] = g_X3[node * 256 + t];
    row[774 + t] = g_X4[node * 256 + t];
}

// ---------------- mean-pool over the 512 nodes of each batch ----------------
__global__ void pool_kernel() {
    int b = blockIdx.x, t = threadIdx.x;  // 256 threads
    float s = 0.f;
    for (int i = 0; i < NPTS; i++)
        s += g_H2[(size_t)(b * NPTS + i) * 256 + t];
    g_POOL[b * 256 + t] = s * (1.f / NPTS);
}

// ---------------- head ------------------------------------------------------
__global__ void final_kernel(const float* __restrict__ w1, const float* __restrict__ b1,
                             const float* __restrict__ w2, const float* __restrict__ b2,
                             float* __restrict__ out) {
    __shared__ float h[128];
    int b = blockIdx.x, t = threadIdx.x;  // 128 threads
    float acc = b1[t];
    for (int c = 0; c < 256; c++) acc = fmaf(g_POOL[b * 256 + c], w1[c * 128 + t], acc);
    h[t] = lrelu(acc);
    __syncthreads();
    if (t < 3) {
        float o = b2[t];
        for (int c = 0; c < 128; c++) o = fmaf(h[c], w2[c * 3 + t], o);
        out[b * 3 + t] = o;
    }
}

// ---------------- launcher ---------------------------------------------------
extern "C" void kernel_launch(void* const* d_in, const int* in_sizes, int n_in,
                              void* d_out, int out_size) {
    (void)in_sizes; (void)n_in; (void)out_size;
    const float* x0 = (const float*)d_in[0];
    const float* cw1[4] = { (const float*)d_in[3],  (const float*)d_in[7],
                            (const float*)d_in[11], (const float*)d_in[15] };
    const float* cb1[4] = { (const float*)d_in[4],  (const float*)d_in[8],
                            (const float*)d_in[12], (const float*)d_in[16] };
    const float* cw2[4] = { (const float*)d_in[5],  (const float*)d_in[9],
                            (const float*)d_in[13], (const float*)d_in[17] };
    const float* cb2[4] = { (const float*)d_in[6],  (const float*)d_in[10],
                            (const float*)d_in[14], (const float*)d_in[18] };
    const float* m1w1 = (const float*)d_in[19];
    const float* m1b1 = (const float*)d_in[20];
    const float* m1w2 = (const float*)d_in[21];
    const float* m1b2 = (const float*)d_in[22];
    const float* m2w1 = (const float*)d_in[23];
    const float* m2b1 = (const float*)d_in[24];
    const float* m2w2 = (const float*)d_in[25];
    const float* m2b2 = (const float*)d_in[26];

    void* p;
    float *pX[4], *pU, *pV, *pH1, *pH2, *pCAT, *pWd;
    cudaGetSymbolAddress(&p, g_X1);  pX[0] = (float*)p;
    cudaGetSymbolAddress(&p, g_X2);  pX[1] = (float*)p;
    cudaGetSymbolAddress(&p, g_X3);  pX[2] = (float*)p;
    cudaGetSymbolAddress(&p, g_X4);  pX[3] = (float*)p;
    cudaGetSymbolAddress(&p, g_U);   pU    = (float*)p;
    cudaGetSymbolAddress(&p, g_V);   pV    = (float*)p;
    cudaGetSymbolAddress(&p, g_H1);  pH1   = (float*)p;
    cudaGetSymbolAddress(&p, g_H2);  pH2   = (float*)p;
    cudaGetSymbolAddress(&p, g_CAT); pCAT  = (float*)p;
    cudaGetSymbolAddress(&p, g_Wd);  pWd   = (float*)p;

    for (int l = 0; l < 4; l++) {
        const float* Xin = (l == 0) ? x0 : pX[l - 1];
        int F = (l == 0) ? 6 : 256;

        norms_kernel<<<BNODES / 8, 256>>>(Xin, F);
        dist_kernel<<<dim3(4, 4, BB), 256>>>(Xin, F);
        topk_kernel<<<BNODES * 32 / 128, 128>>>();
        wdiff_kernel<<<(F * 336 + 255) / 256, 256>>>(cw1[l], F);
        if (l == 0) {
            gemm_kernel<<<dim3(3, BNODES / 128), 256>>>(Xin, pWd, nullptr, pU,
                                                        BNODES, F, 336, F, 0);
            gemm_kernel<<<dim3(3, BNODES / 128), 256>>>(Xin, cw1[l] + (size_t)F * 336,
                                                        nullptr, pV, BNODES, F, 336, F, 0);
        } else {
            gemm_tf32_kernel<<<dim3(3, BNODES / 128), 256>>>(Xin, pWd, nullptr, pU,
                                                             256, 256, 336, 256, 0);
            gemm_tf32_kernel<<<dim3(3, BNODES / 128), 256>>>(Xin, cw1[l] + (size_t)F * 336,
                                                             nullptr, pV, 256, 256, 336, 256, 0);
        }
        // fused: H1 on the fly, GEMM2 (tf32 tensor), max over K, bias, lrelu
        edge_gemm2_kernel<<<dim3(2, NEDGE / 128), 256>>>(cb1[l], cw2[l], cb2[l], pX[l]);
    }

    concat_kernel<<<BNODES, 256>>>(x0);
    // m1: 1030 -> 336 -> 256, both LeakyReLU (tf32)
    gemm_tf32_kernel<<<dim3(3, BNODES / 128), 256>>>(pCAT, m1w1, m1b1, pH1,
                                                     1040, 1030, 336, 1040, 1);
    gemm_tf32_kernel<<<dim3(2, BNODES / 128), 256>>>(pH1, m1w2, m1b2, pH2,
                                                     336, 336, 256, 336, 1);
    pool_kernel<<<BB, 256>>>();
    final_kernel<<<BB, 128>>>(m2w1, m2b1, m2w2, m2b2, (float*)d_out);
}